// round 8
// baseline (speedup 1.0000x reference)
#include <cuda_runtime.h>

typedef unsigned long long u64;
typedef unsigned int u32;

__device__ __forceinline__ u64 pack2(float x, float y) {
    u64 r; asm("mov.b64 %0, {%1, %2};" : "=l"(r) : "f"(x), "f"(y)); return r;
}
__device__ __forceinline__ u64 pack2dup(float x) {
    u64 r; asm("mov.b64 %0, {%1, %1};" : "=l"(r) : "f"(x)); return r;
}
__device__ __forceinline__ void unpack2(u64 v, float& x, float& y) {
    asm("mov.b64 {%0, %1}, %2;" : "=f"(x), "=f"(y) : "l"(v));
}
__device__ __forceinline__ u64 ffma2(u64 a, u64 b, u64 c) {
    u64 d; asm("fma.rn.f32x2 %0, %1, %2, %3;" : "=l"(d) : "l"(a), "l"(b), "l"(c));
    return d;
}

#define HS 36   // H row stride

// pool layout (floats), 13376 total:
//  At8 (2x1024 u32) @0 | H0g0 @2048 | H0g1 @4352 | H1g0 @6656 | H1g1 @8960
//  WB @11264 (2112): w1+0, b1+1024, w2+1056, b2+2080
// conv overlays:
//  conv1 w @0 (5280, stride 165) + bias @5280  (over At8+H0g0+H0g1head, all dead)
//  pooledT @11264 + gb*384 (in dead WB)
//  per-graph (in own dead H1): partials +0 (4x352), ybufT +1408 (32x8),
//  c2buf +1664 (80), feat +1824, hid +1840
//  conv2 w @0 (2640, stride 165) + bias @2640
#define L_H0G0 2048
#define L_H0G1 4352
#define L_H1G0 6656
#define L_H1G1 8960
#define L_WB   11264
#define SMEM_FLOATS 13376
#define L_C1B  5280
#define L_C2B  2640

// ---- agg: Z[n][c] = sum_k A[n][k]*H[k][c]; A byte-packed (incl. diag) ----
template<int W>
__device__ __forceinline__ void agg_frag(const u32* __restrict__ At8,
                                         const float* __restrict__ H,
                                         float* __restrict__ Z, int tl)
{
    constexpr int PP = W / 16;
    const int warp = tl >> 5, lane = tl & 31;
    const int ni = lane >> 2, ci = lane & 3;
    const int nhalf = (warp & 1) * 32;
    const int chalf = (warp >> 1) * (W / 2);
    const int c0 = chalf + ci * (2 * PP);

    u64 acc[4][PP];
    #pragma unroll
    for (int g = 0; g < 4; g++)
        #pragma unroll
        for (int p = 0; p < PP; p++) acc[g][p] = 0ull;

    #pragma unroll 2
    for (int kb = 0; kb < 16; kb++) {
        u32 a4[4];
        #pragma unroll
        for (int g = 0; g < 4; g++)
            a4[g] = At8[kb * 64 + nhalf + ni + 8 * g];
        #pragma unroll
        for (int j = 0; j < 4; j++) {
            const int k = 4 * kb + j;
            u64 h[PP];
            if (PP == 2) {
                const float4 hv = *(const float4*)&H[k * HS + c0];
                h[0] = pack2(hv.x, hv.y); h[1] = pack2(hv.z, hv.w);
            } else {
                const float2 hv = *(const float2*)&H[k * HS + c0];
                h[0] = pack2(hv.x, hv.y);
            }
            #pragma unroll
            for (int g = 0; g < 4; g++) {
                const float af = (float)((a4[g] >> (8 * j)) & 0xffu);
                const u64 ad = pack2dup(af);
                #pragma unroll
                for (int p = 0; p < PP; p++)
                    acc[g][p] = ffma2(ad, h[p], acc[g][p]);
            }
        }
    }
    #pragma unroll
    for (int g = 0; g < 4; g++) {
        const int n = nhalf + ni + 8 * g;
        if (PP == 2) {
            float x0, y0, x1, y1;
            unpack2(acc[g][0], x0, y0); unpack2(acc[g][1], x1, y1);
            *(float4*)&Z[n * HS + c0] = make_float4(x0, y0, x1, y1);
        } else {
            float x0, y0;
            unpack2(acc[g][0], x0, y0);
            *(float2*)&Z[n * HS + c0] = make_float2(x0, y0);
        }
    }
}

// ---- gemm: Out[n][o] = relu(B[o] + sum_k Zin[n][k]*W[k][o]); 64x32 ----
template<int DIN>
__device__ __forceinline__ void gemm_frag(const float* __restrict__ Zin,
                                          float* __restrict__ Out,
                                          const float* __restrict__ W,
                                          const float* __restrict__ B, int tl)
{
    const int warp = tl >> 5, lane = tl & 31;
    const int ni = lane >> 2, oi = lane & 3;
    const int nhalf = (warp & 1) * 32;
    const int o0 = (warp >> 1) * 16 + 4 * oi;

    u64 acc[4][2];
    {
        const float4 b4 = *(const float4*)&B[o0];
        const u64 b01 = pack2(b4.x, b4.y), b23 = pack2(b4.z, b4.w);
        #pragma unroll
        for (int g = 0; g < 4; g++) { acc[g][0] = b01; acc[g][1] = b23; }
    }
    #pragma unroll
    for (int kb = 0; kb < DIN / 4; kb++) {
        float4 zf[4];
        #pragma unroll
        for (int g = 0; g < 4; g++)
            zf[g] = *(const float4*)&Zin[(nhalf + ni + 8 * g) * HS + 4 * kb];
        #pragma unroll
        for (int j = 0; j < 4; j++) {
            const int k = 4 * kb + j;
            const float4 wv = *(const float4*)&W[k * 32 + o0];
            const u64 w01 = pack2(wv.x, wv.y), w23 = pack2(wv.z, wv.w);
            #pragma unroll
            for (int g = 0; g < 4; g++) {
                const float a = (j == 0) ? zf[g].x : (j == 1) ? zf[g].y :
                                (j == 2) ? zf[g].z : zf[g].w;
                const u64 ad = pack2dup(a);
                acc[g][0] = ffma2(ad, w01, acc[g][0]);
                acc[g][1] = ffma2(ad, w23, acc[g][1]);
            }
        }
    }
    #pragma unroll
    for (int g = 0; g < 4; g++) {
        float x0, y0, x1, y1;
        unpack2(acc[g][0], x0, y0); unpack2(acc[g][1], x1, y1);
        *(float4*)&Out[(nhalf + ni + 8 * g) * HS + o0] =
            make_float4(fmaxf(x0, 0.f), fmaxf(y0, 0.f),
                        fmaxf(x1, 0.f), fmaxf(y1, 0.f));
    }
}

__global__ void __launch_bounds__(256, 4)
seal_kernel(
    const int* __restrict__ labels,
    const int* __restrict__ src,
    const int* __restrict__ dst,
    const float* __restrict__ emb,
    const float* __restrict__ w1_0, const float* __restrict__ b1_0,
    const float* __restrict__ w2_0, const float* __restrict__ b2_0,
    const float* __restrict__ w1_1, const float* __restrict__ b1_1,
    const float* __restrict__ w2_1, const float* __restrict__ b2_1,
    const float* __restrict__ w1_2, const float* __restrict__ b1_2,
    const float* __restrict__ w2_2, const float* __restrict__ b2_2,
    const float* __restrict__ conv1_w, const float* __restrict__ conv1_b,
    const float* __restrict__ conv2_w, const float* __restrict__ conv2_b,
    const float* __restrict__ sc_w1, const float* __restrict__ sc_b1,
    const float* __restrict__ sc_w2, const float* __restrict__ sc_b2,
    float* __restrict__ out)
{
    extern __shared__ __align__(16) float pool[];
    __shared__ int nor[2][10];

    const int t  = threadIdx.x;
    const int tl = t & 127;          // tid within half-CTA
    const int gb = t >> 7;           // 0 or 1: which graph of the pair
    const int g  = blockIdx.x * 2 + gb;

    u32*   At8 = (u32*)pool + gb * 1024;
    float* H0  = pool + (gb ? L_H0G1 : L_H0G0);
    float* H1  = pool + (gb ? L_H1G1 : L_H1G0);
    float* WB  = pool + L_WB;
    float* HP  = pool + (gb ? L_H1G1 : L_H1G0);   // conv scratch (dead H1)
    float* PT  = pool + L_WB + gb * 384;          // pooledT (dead WB)

    // ---- zero packed adjacency (own half) ----
    {
        const uint4 z4 = make_uint4(0u, 0u, 0u, 0u);
        *(uint4*)(At8 + tl * 4)         = z4;
        *(uint4*)(At8 + (tl + 128) * 4) = z4;
    }
    __syncthreads();

    // ---- edges + diagonal into byte-packed At8; embedding load ----
    {
        const int4* s4p = (const int4*)(src + ((long)g << 10));
        const int4* d4p = (const int4*)(dst + ((long)g << 10));
        #pragma unroll
        for (int i = 0; i < 2; i++) {
            const int4 s = s4p[tl + i * 128];
            const int4 d = d4p[tl + i * 128];
            const int sx = s.x & 63, sy = s.y & 63, sz = s.z & 63, sw = s.w & 63;
            atomicAdd(&At8[(sx >> 2) * 64 + (d.x & 63)], 1u << (8 * (sx & 3)));
            atomicAdd(&At8[(sy >> 2) * 64 + (d.y & 63)], 1u << (8 * (sy & 3)));
            atomicAdd(&At8[(sz >> 2) * 64 + (d.z & 63)], 1u << (8 * (sz & 3)));
            atomicAdd(&At8[(sw >> 2) * 64 + (d.w & 63)], 1u << (8 * (sw & 3)));
        }
        if (tl < 64) atomicAdd(&At8[(tl >> 2) * 64 + tl], 1u << (8 * (tl & 3)));
    }
    {
        const int n = tl >> 1, c0 = (tl & 1) * 8;
        const float4 v0 = *(const float4*)(emb + labels[(g << 6) + n] * 16 + c0);
        const float4 v1 = *(const float4*)(emb + labels[(g << 6) + n] * 16 + c0 + 4);
        *(float4*)(H0 + n * HS + c0)     = v0;
        *(float4*)(H0 + n * HS + c0 + 4) = v1;
    }
    __syncthreads();

    const float* W1s[3] = { w1_0, w1_1, w1_2 };
    const float* B1s[3] = { b1_0, b1_1, b1_2 };
    const float* W2s[3] = { w2_0, w2_1, w2_2 };
    const float* B2s[3] = { b2_0, b2_1, b2_2 };

    float* cur = H0;
    float* oth = H1;

    #pragma unroll
    for (int l = 0; l < 3; l++) {
        const int din = l ? 32 : 16;

        // stage layer weights once for both graphs (all 256 threads)
        for (int idx = t; idx < din * 8; idx += 256)
            *(float4*)(WB + idx * 4) = *(const float4*)(W1s[l] + idx * 4);
        for (int idx = t; idx < 256; idx += 256)
            *(float4*)(WB + 1056 + idx * 4) = *(const float4*)(W2s[l] + idx * 4);
        if (t < 32)            WB[1024 + t] = B1s[l][t];
        if (t >= 32 && t < 64) WB[2080 + (t - 32)] = B2s[l][t - 32];
        __syncthreads();

        if (din == 16) agg_frag<16>(At8, cur, oth, tl);
        else           agg_frag<32>(At8, cur, oth, tl);
        __syncthreads();

        if (din == 16) gemm_frag<16>(oth, cur, WB, WB + 1024, tl);
        else           gemm_frag<32>(oth, cur, WB, WB + 1024, tl);
        __syncthreads();

        gemm_frag<32>(cur, oth, WB + 1056, WB + 2080, tl);
        __syncthreads();

        float* tmp = cur; cur = oth; oth = tmp;
    }
    // cur == H1 for each graph

    // ---- SortPooling: stable rank by channel 31 desc, keep 10 ----
    if (tl < 64) {
        const float key = cur[tl * HS + 31];
        int r = 0;
        for (int m = 0; m < 64; m++) {
            const float km = cur[m * HS + 31];
            r += (km > key) || (km == key && m < tl);
        }
        if (r < 10) nor[gb][r] = tl;
    }
    __syncthreads();

    // ---- pooledT extraction into dead WB region ----
    for (int idx = tl; idx < 384; idx += 128) {
        const int ci = idx / 12, r = idx - ci * 12;
        PT[ci * 12 + r] = (r < 10) ? cur[nor[gb][r] * HS + ci] : 0.f;
    }
    __syncthreads();

    // ---- conv1 weight staging once for both graphs (dead At8+H0 region) ----
    for (int idx = t; idx < 5120; idx += 256) {
        const int co = idx / 160, r = idx - co * 160;
        pool[co * 165 + r] = conv1_w[idx];
    }
    if (t < 32) pool[L_C1B + t] = conv1_b[t];
    __syncthreads();

    // ---- Conv1: per graph, 4 warps x 8 input channels; lane = co ----
    {
        const int wl = tl >> 5, lane = tl & 31;
        float acc[10];
        #pragma unroll
        for (int p = 0; p < 10; p++) acc[p] = 0.f;
        for (int ci = wl * 8; ci < wl * 8 + 8; ci++) {
            float w[5];
            #pragma unroll
            for (int k = 0; k < 5; k++) w[k] = pool[lane * 165 + ci * 5 + k];
            const float4 va = *(const float4*)&PT[ci * 12];
            const float4 vb = *(const float4*)&PT[ci * 12 + 4];
            const float4 vc = *(const float4*)&PT[ci * 12 + 8];
            const float v[12] = { va.x, va.y, va.z, va.w, vb.x, vb.y, vb.z, vb.w,
                                  vc.x, vc.y, vc.z, vc.w };
            #pragma unroll
            for (int p = 0; p < 10; p++) {
                #pragma unroll
                for (int k = 0; k < 5; k++) {
                    const int idx = p + k - 2;
                    if (idx >= 0) acc[p] = fmaf(w[k], v[idx], acc[p]);
                }
            }
        }
        #pragma unroll
        for (int p = 0; p < 10; p++)
            HP[wl * 352 + lane * 11 + p] = acc[p];     // stride 11: conflict-free
    }
    __syncthreads();

    // ---- combine partials -> ybufT (per graph) + conv2 staging (all) ----
    if (tl < 32) {
        const int co = tl;
        float y[5];
        #pragma unroll
        for (int q = 0; q < 5; q++) {
            float v0 = pool[L_C1B + co], v1 = v0;
            #pragma unroll
            for (int w = 0; w < 4; w++) {
                v0 += HP[w * 352 + co * 11 + 2 * q];
                v1 += HP[w * 352 + co * 11 + 2 * q + 1];
            }
            y[q] = fmaxf(fmaxf(v0, 0.f), fmaxf(v1, 0.f));
        }
        #pragma unroll
        for (int q = 0; q < 5; q++) HP[1408 + co * 8 + q] = y[q];
        HP[1408 + co * 8 + 5] = 0.f;
        HP[1408 + co * 8 + 6] = 0.f;
        HP[1408 + co * 8 + 7] = 0.f;
    }
    __syncthreads();   // conv1 weights fully consumed

    for (int idx = t; idx < 2560; idx += 256) {
        const int co = idx / 160, r = idx - co * 160;
        pool[co * 165 + r] = conv2_w[idx];
    }
    if (t < 16) pool[L_C2B + t] = conv2_b[t];
    __syncthreads();

    // ---- Conv2 per graph: lane<16 = co; p = 0..4 ----
    if (tl < 16) {
        float acc[5];
        #pragma unroll
        for (int p = 0; p < 5; p++) acc[p] = pool[L_C2B + tl];
        for (int ci = 0; ci < 32; ci++) {
            float w[5];
            #pragma unroll
            for (int k = 0; k < 5; k++) w[k] = pool[tl * 165 + ci * 5 + k];
            const float4 ya = *(const float4*)&HP[1408 + ci * 8];
            const float y4 = HP[1408 + ci * 8 + 4];
            const float a[9] = { 0.f, 0.f, ya.x, ya.y, ya.z, ya.w, y4, 0.f, 0.f };
            #pragma unroll
            for (int p = 0; p < 5; p++)
                #pragma unroll
                for (int k = 0; k < 5; k++)
                    acc[p] = fmaf(w[k], a[p + k], acc[p]);
        }
        #pragma unroll
        for (int p = 0; p < 5; p++)
            HP[1664 + tl * 5 + p] = fmaxf(acc[p], 0.f);
    }
    __syncthreads();

    // ---- mean + scorer MLP (per graph; scorer weights from global) ----
    if (tl < 16) {
        HP[1824 + tl] = 0.2f * (HP[1664 + tl * 5 + 0] + HP[1664 + tl * 5 + 1] +
                                HP[1664 + tl * 5 + 2] + HP[1664 + tl * 5 + 3] +
                                HP[1664 + tl * 5 + 4]);
    }
    __syncthreads();
    if (tl < 16) {
        float a = sc_b1[tl];
        #pragma unroll
        for (int i = 0; i < 16; i++) a = fmaf(HP[1824 + i], sc_w1[i * 16 + tl], a);
        HP[1840 + tl] = fmaxf(a, 0.f);
    }
    __syncthreads();
    if (tl == 0) {
        float s = sc_b2[0];
        #pragma unroll
        for (int j = 0; j < 16; j++) s = fmaf(HP[1840 + j], sc_w2[j], s);
        out[g] = s;
    }
}

extern "C" void kernel_launch(void* const* d_in, const int* in_sizes, int n_in,
                              void* d_out, int out_size)
{
    const int B = in_sizes[0] / 64;
    const int smem = SMEM_FLOATS * sizeof(float);   // 53504 B
    cudaFuncSetAttribute(seal_kernel,
                         cudaFuncAttributeMaxDynamicSharedMemorySize, smem);
    seal_kernel<<<B / 2, 256, smem>>>(
        (const int*)d_in[0], (const int*)d_in[1], (const int*)d_in[2],
        (const float*)d_in[3],
        (const float*)d_in[4],  (const float*)d_in[5],
        (const float*)d_in[6],  (const float*)d_in[7],
        (const float*)d_in[8],  (const float*)d_in[9],
        (const float*)d_in[10], (const float*)d_in[11],
        (const float*)d_in[12], (const float*)d_in[13],
        (const float*)d_in[14], (const float*)d_in[15],
        (const float*)d_in[16], (const float*)d_in[17],
        (const float*)d_in[18], (const float*)d_in[19],
        (const float*)d_in[20], (const float*)d_in[21],
        (const float*)d_in[22], (const float*)d_in[23],
        (float*)d_out);
}

// round 9
// speedup vs baseline: 1.0443x; 1.0443x over previous
#include <cuda_runtime.h>

typedef unsigned long long u64;
typedef unsigned int u32;

__device__ __forceinline__ u64 pack2(float x, float y) {
    u64 r; asm("mov.b64 %0, {%1, %2};" : "=l"(r) : "f"(x), "f"(y)); return r;
}
__device__ __forceinline__ u64 pack2dup(float x) {
    u64 r; asm("mov.b64 %0, {%1, %1};" : "=l"(r) : "f"(x)); return r;
}
__device__ __forceinline__ void unpack2(u64 v, float& x, float& y) {
    asm("mov.b64 {%0, %1}, %2;" : "=f"(x), "=f"(y) : "l"(v));
}
__device__ __forceinline__ u64 ffma2(u64 a, u64 b, u64 c) {
    u64 d; asm("fma.rn.f32x2 %0, %1, %2, %3;" : "=l"(d) : "l"(a), "l"(b), "l"(c));
    return d;
}

#define HS 36   // H row stride

// pool layout (floats), 7792 total:
//  GIN : At8 (1024 u32) @0 | H0 @1024..3328 | H1 @3328..5632 | WB @5632..7744
//        WB: w1 +0 (1024), b1 +1024 (32), w2 +1056 (1024), b2 +2080 (32)
//  conv overlays (GIN buffers dead in order):
//        conv1 w @0 (5280, stride 165) + bias @5280
//        pooledT @5632 (384) | partials @6016 (4 x 352, stride 11)
//        ybufT @7424 (32x8) | c2buf @7680 (80) | feat @7760 | hid @7776
//        conv2 w @0 (2640, stride 165) + bias @2640
#define P_H0   1024
#define P_H1   3328
#define P_WB   5632
#define P_C1B  5280
#define P_PT   5632
#define P_PART 6016
#define P_YB   7424
#define P_C2   7680
#define P_FE   7760
#define P_HI   7776
#define P_C2B  2640

// ---- weight staging (pipelined into compute phases) ----
__device__ __forceinline__ void stage_w1(const float* __restrict__ W1,
                                         const float* __restrict__ B1,
                                         float* __restrict__ WB, int din, int t)
{
    for (int idx = t; idx < din * 8; idx += 128)
        *(float4*)(WB + idx * 4) = *(const float4*)(W1 + idx * 4);
    if (t < 32) WB[1024 + t] = B1[t];
}
__device__ __forceinline__ void stage_w2(const float* __restrict__ W2,
                                         const float* __restrict__ B2,
                                         float* __restrict__ WB, int t)
{
    for (int idx = t; idx < 256; idx += 128)
        *(float4*)(WB + 1056 + idx * 4) = *(const float4*)(W2 + idx * 4);
    if (t >= 32 && t < 64) WB[2080 + (t - 32)] = B2[t - 32];
}

// ---- agg: Z[n][c] = sum_k A[n][k]*H[k][c]; A byte-packed (incl. diag) ----
template<int W>
__device__ __forceinline__ void agg_frag(const u32* __restrict__ At8,
                                         const float* __restrict__ H,
                                         float* __restrict__ Z, int t)
{
    constexpr int PP = W / 16;
    const int warp = t >> 5, lane = t & 31;
    const int ni = lane >> 2, ci = lane & 3;
    const int nhalf = (warp & 1) * 32;
    const int chalf = (warp >> 1) * (W / 2);
    const int c0 = chalf + ci * (2 * PP);

    u64 acc[4][PP];
    #pragma unroll
    for (int g = 0; g < 4; g++)
        #pragma unroll
        for (int p = 0; p < PP; p++) acc[g][p] = 0ull;

    #pragma unroll 2
    for (int kb = 0; kb < 16; kb++) {
        u32 a4[4];
        #pragma unroll
        for (int g = 0; g < 4; g++)
            a4[g] = At8[kb * 64 + nhalf + ni + 8 * g];
        #pragma unroll
        for (int j = 0; j < 4; j++) {
            const int k = 4 * kb + j;
            u64 h[PP];
            if (PP == 2) {
                const float4 hv = *(const float4*)&H[k * HS + c0];
                h[0] = pack2(hv.x, hv.y); h[1] = pack2(hv.z, hv.w);
            } else {
                const float2 hv = *(const float2*)&H[k * HS + c0];
                h[0] = pack2(hv.x, hv.y);
            }
            #pragma unroll
            for (int g = 0; g < 4; g++) {
                const float af = (float)((a4[g] >> (8 * j)) & 0xffu);
                const u64 ad = pack2dup(af);
                #pragma unroll
                for (int p = 0; p < PP; p++)
                    acc[g][p] = ffma2(ad, h[p], acc[g][p]);
            }
        }
    }
    #pragma unroll
    for (int g = 0; g < 4; g++) {
        const int n = nhalf + ni + 8 * g;
        if (PP == 2) {
            float x0, y0, x1, y1;
            unpack2(acc[g][0], x0, y0); unpack2(acc[g][1], x1, y1);
            *(float4*)&Z[n * HS + c0] = make_float4(x0, y0, x1, y1);
        } else {
            float x0, y0;
            unpack2(acc[g][0], x0, y0);
            *(float2*)&Z[n * HS + c0] = make_float2(x0, y0);
        }
    }
}

// ---- gemm: Out[n][o] = relu(B[o] + sum_k Zin[n][k]*W[k][o]); 64x32 ----
template<int DIN>
__device__ __forceinline__ void gemm_frag(const float* __restrict__ Zin,
                                          float* __restrict__ Out,
                                          const float* __restrict__ W,
                                          const float* __restrict__ B, int t)
{
    const int warp = t >> 5, lane = t & 31;
    const int ni = lane >> 2, oi = lane & 3;
    const int nhalf = (warp & 1) * 32;
    const int o0 = (warp >> 1) * 16 + 4 * oi;

    u64 acc[4][2];
    {
        const float4 b4 = *(const float4*)&B[o0];
        const u64 b01 = pack2(b4.x, b4.y), b23 = pack2(b4.z, b4.w);
        #pragma unroll
        for (int g = 0; g < 4; g++) { acc[g][0] = b01; acc[g][1] = b23; }
    }
    #pragma unroll
    for (int kb = 0; kb < DIN / 4; kb++) {
        float4 zf[4];
        #pragma unroll
        for (int g = 0; g < 4; g++)
            zf[g] = *(const float4*)&Zin[(nhalf + ni + 8 * g) * HS + 4 * kb];
        #pragma unroll
        for (int j = 0; j < 4; j++) {
            const int k = 4 * kb + j;
            const float4 wv = *(const float4*)&W[k * 32 + o0];
            const u64 w01 = pack2(wv.x, wv.y), w23 = pack2(wv.z, wv.w);
            #pragma unroll
            for (int g = 0; g < 4; g++) {
                const float a = (j == 0) ? zf[g].x : (j == 1) ? zf[g].y :
                                (j == 2) ? zf[g].z : zf[g].w;
                const u64 ad = pack2dup(a);
                acc[g][0] = ffma2(ad, w01, acc[g][0]);
                acc[g][1] = ffma2(ad, w23, acc[g][1]);
            }
        }
    }
    #pragma unroll
    for (int g = 0; g < 4; g++) {
        float x0, y0, x1, y1;
        unpack2(acc[g][0], x0, y0); unpack2(acc[g][1], x1, y1);
        *(float4*)&Out[(nhalf + ni + 8 * g) * HS + o0] =
            make_float4(fmaxf(x0, 0.f), fmaxf(y0, 0.f),
                        fmaxf(x1, 0.f), fmaxf(y1, 0.f));
    }
}

__global__ void __launch_bounds__(128, 7)
seal_kernel(
    const int* __restrict__ labels,
    const int* __restrict__ src,
    const int* __restrict__ dst,
    const float* __restrict__ emb,
    const float* __restrict__ w1_0, const float* __restrict__ b1_0,
    const float* __restrict__ w2_0, const float* __restrict__ b2_0,
    const float* __restrict__ w1_1, const float* __restrict__ b1_1,
    const float* __restrict__ w2_1, const float* __restrict__ b2_1,
    const float* __restrict__ w1_2, const float* __restrict__ b1_2,
    const float* __restrict__ w2_2, const float* __restrict__ b2_2,
    const float* __restrict__ conv1_w, const float* __restrict__ conv1_b,
    const float* __restrict__ conv2_w, const float* __restrict__ conv2_b,
    const float* __restrict__ sc_w1, const float* __restrict__ sc_b1,
    const float* __restrict__ sc_w2, const float* __restrict__ sc_b2,
    float* __restrict__ out)
{
    __shared__ __align__(16) float pool[7792];
    __shared__ int nor[10];

    u32*   At8 = (u32*)pool;
    float* H0  = pool + P_H0;
    float* H1  = pool + P_H1;
    float* WB  = pool + P_WB;

    const int g = blockIdx.x;
    const int t = threadIdx.x;

    // ---- phase 0: zero At8 + prestage layer-0 weights ----
    {
        const uint4 z4 = make_uint4(0u, 0u, 0u, 0u);
        *(uint4*)(At8 + t * 4)         = z4;
        *(uint4*)(At8 + (t + 128) * 4) = z4;
    }
    stage_w1(w1_0, b1_0, WB, 16, t);
    stage_w2(w2_0, b2_0, WB, t);
    __syncthreads();

    // ---- edges + diagonal into byte-packed At8; embedding load ----
    {
        const int4* s4p = (const int4*)(src + ((long)g << 10));
        const int4* d4p = (const int4*)(dst + ((long)g << 10));
        #pragma unroll
        for (int i = 0; i < 2; i++) {
            const int4 s = s4p[t + i * 128];
            const int4 d = d4p[t + i * 128];
            const int sx = s.x & 63, sy = s.y & 63, sz = s.z & 63, sw = s.w & 63;
            atomicAdd(&At8[(sx >> 2) * 64 + (d.x & 63)], 1u << (8 * (sx & 3)));
            atomicAdd(&At8[(sy >> 2) * 64 + (d.y & 63)], 1u << (8 * (sy & 3)));
            atomicAdd(&At8[(sz >> 2) * 64 + (d.z & 63)], 1u << (8 * (sz & 3)));
            atomicAdd(&At8[(sw >> 2) * 64 + (d.w & 63)], 1u << (8 * (sw & 3)));
        }
        if (t < 64) atomicAdd(&At8[(t >> 2) * 64 + t], 1u << (8 * (t & 3)));
    }
    {
        const int n = t >> 1, c0 = (t & 1) * 8;
        const float4 v0 = *(const float4*)(emb + labels[(g << 6) + n] * 16 + c0);
        const float4 v1 = *(const float4*)(emb + labels[(g << 6) + n] * 16 + c0 + 4);
        *(float4*)(H0 + n * HS + c0)     = v0;
        *(float4*)(H0 + n * HS + c0 + 4) = v1;
    }
    __syncthreads();

    // ---- layer 0 ----
    agg_frag<16>(At8, H0, H1, t);
    __syncthreads();
    gemm_frag<16>(H1, H0, WB, WB + 1024, t);
    __syncthreads();
    gemm_frag<32>(H0, H1, WB + 1056, WB + 2080, t);   // -> H1
    stage_w1(w1_1, b1_1, WB, 32, t);                  // w1 slot dead here
    __syncthreads();

    // ---- layer 1 (cur = H1) ----
    agg_frag<32>(At8, H1, H0, t);
    stage_w2(w2_1, b2_1, WB, t);                      // w2 slot dead here
    __syncthreads();
    gemm_frag<32>(H0, H1, WB, WB + 1024, t);
    __syncthreads();
    gemm_frag<32>(H1, H0, WB + 1056, WB + 2080, t);   // -> H0
    stage_w1(w1_2, b1_2, WB, 32, t);
    __syncthreads();

    // ---- layer 2 (cur = H0) ----
    agg_frag<32>(At8, H0, H1, t);
    stage_w2(w2_2, b2_2, WB, t);
    __syncthreads();
    gemm_frag<32>(H1, H0, WB, WB + 1024, t);
    __syncthreads();
    gemm_frag<32>(H0, H1, WB + 1056, WB + 2080, t);   // FINAL -> H1
    __syncthreads();

    float* cur = H1;

    // ---- SortPooling: stable rank by channel 31 desc, keep 10 ----
    if (t < 64) {
        const float key = cur[t * HS + 31];
        int r = 0;
        for (int m = 0; m < 64; m++) {
            const float km = cur[m * HS + 31];
            r += (km > key) || (km == key && m < t);
        }
        if (r < 10) nor[r] = t;
    }
    __syncthreads();

    // ---- pooledT extraction (before conv1 staging kills H1) ----
    for (int idx = t; idx < 384; idx += 128) {
        const int ci = idx / 12, r = idx - ci * 12;
        pool[P_PT + ci * 12 + r] = (r < 10) ? cur[nor[r] * HS + ci] : 0.f;
    }
    __syncthreads();

    // ---- conv1 weight staging (overwrites At8/H0/H1 head — all dead) ----
    for (int idx = t; idx < 5120; idx += 128) {
        const int co = idx / 160, r = idx - co * 160;
        pool[co * 165 + r] = conv1_w[idx];
    }
    if (t < 32) pool[P_C1B + t] = conv1_b[t];
    __syncthreads();

    // ---- Conv1: 4 warps x 8 input channels; lane = co ----
    {
        const int warp = t >> 5, lane = t & 31;
        float acc[10];
        #pragma unroll
        for (int p = 0; p < 10; p++) acc[p] = 0.f;
        for (int ci = warp * 8; ci < warp * 8 + 8; ci++) {
            float w[5];
            #pragma unroll
            for (int k = 0; k < 5; k++) w[k] = pool[lane * 165 + ci * 5 + k];
            const float4 va = *(const float4*)&pool[P_PT + ci * 12];
            const float4 vb = *(const float4*)&pool[P_PT + ci * 12 + 4];
            const float4 vc = *(const float4*)&pool[P_PT + ci * 12 + 8];
            const float v[12] = { va.x, va.y, va.z, va.w, vb.x, vb.y, vb.z, vb.w,
                                  vc.x, vc.y, vc.z, vc.w };
            #pragma unroll
            for (int p = 0; p < 10; p++) {
                #pragma unroll
                for (int k = 0; k < 5; k++) {
                    const int idx = p + k - 2;
                    if (idx >= 0) acc[p] = fmaf(w[k], v[idx], acc[p]);
                }
            }
        }
        #pragma unroll
        for (int p = 0; p < 10; p++)
            pool[P_PART + warp * 352 + lane * 11 + p] = acc[p];  // stride 11
    }
    __syncthreads();

    // ---- combine partials + bias + relu + maxpool -> ybufT ----
    if (t < 32) {
        const int co = t;
        float y[5];
        #pragma unroll
        for (int q = 0; q < 5; q++) {
            float v0 = pool[P_C1B + co], v1 = v0;
            #pragma unroll
            for (int w = 0; w < 4; w++) {
                v0 += pool[P_PART + w * 352 + co * 11 + 2 * q];
                v1 += pool[P_PART + w * 352 + co * 11 + 2 * q + 1];
            }
            y[q] = fmaxf(fmaxf(v0, 0.f), fmaxf(v1, 0.f));
        }
        #pragma unroll
        for (int q = 0; q < 5; q++) pool[P_YB + co * 8 + q] = y[q];
        pool[P_YB + co * 8 + 5] = 0.f;
        pool[P_YB + co * 8 + 6] = 0.f;
        pool[P_YB + co * 8 + 7] = 0.f;
    }
    for (int idx = t; idx < 2560; idx += 128) {
        const int co = idx / 160, r = idx - co * 160;
        pool[co * 165 + r] = conv2_w[idx];        // conv1 w dead
    }
    if (t >= 112 && t < 128) pool[P_C2B + (t - 112)] = conv2_b[t - 112];
    __syncthreads();

    // ---- Conv2: lane<16 = co; p = 0..4 ----
    if (t < 16) {
        float acc[5];
        #pragma unroll
        for (int p = 0; p < 5; p++) acc[p] = pool[P_C2B + t];
        for (int ci = 0; ci < 32; ci++) {
            float w[5];
            #pragma unroll
            for (int k = 0; k < 5; k++) w[k] = pool[t * 165 + ci * 5 + k];
            const float4 ya = *(const float4*)&pool[P_YB + ci * 8];
            const float y4 = pool[P_YB + ci * 8 + 4];
            const float a[9] = { 0.f, 0.f, ya.x, ya.y, ya.z, ya.w, y4, 0.f, 0.f };
            #pragma unroll
            for (int p = 0; p < 5; p++)
                #pragma unroll
                for (int k = 0; k < 5; k++)
                    acc[p] = fmaf(w[k], a[p + k], acc[p]);
        }
        #pragma unroll
        for (int p = 0; p < 5; p++)
            pool[P_C2 + t * 5 + p] = fmaxf(acc[p], 0.f);
    }
    __syncthreads();

    if (t < 16) {
        pool[P_FE + t] = 0.2f * (pool[P_C2 + t * 5 + 0] + pool[P_C2 + t * 5 + 1] +
                                 pool[P_C2 + t * 5 + 2] + pool[P_C2 + t * 5 + 3] +
                                 pool[P_C2 + t * 5 + 4]);
    }
    __syncthreads();
    if (t < 16) {
        float a = sc_b1[t];
        #pragma unroll
        for (int i = 0; i < 16; i++) a = fmaf(pool[P_FE + i], sc_w1[i * 16 + t], a);
        pool[P_HI + t] = fmaxf(a, 0.f);
    }
    __syncthreads();
    if (t == 0) {
        float s = sc_b2[0];
        #pragma unroll
        for (int j = 0; j < 16; j++) s = fmaf(pool[P_HI + j], sc_w2[j], s);
        out[g] = s;
    }
}

extern "C" void kernel_launch(void* const* d_in, const int* in_sizes, int n_in,
                              void* d_out, int out_size)
{
    const int B = in_sizes[0] / 64;
    seal_kernel<<<B, 128>>>(
        (const int*)d_in[0], (const int*)d_in[1], (const int*)d_in[2],
        (const float*)d_in[3],
        (const float*)d_in[4],  (const float*)d_in[5],
        (const float*)d_in[6],  (const float*)d_in[7],
        (const float*)d_in[8],  (const float*)d_in[9],
        (const float*)d_in[10], (const float*)d_in[11],
        (const float*)d_in[12], (const float*)d_in[13],
        (const float*)d_in[14], (const float*)d_in[15],
        (const float*)d_in[16], (const float*)d_in[17],
        (const float*)d_in[18], (const float*)d_in[19],
        (const float*)d_in[20], (const float*)d_in[21],
        (const float*)d_in[22], (const float*)d_in[23],
        (float*)d_out);
}

// round 10
// speedup vs baseline: 1.0920x; 1.0457x over previous
#include <cuda_runtime.h>

typedef unsigned long long u64;
typedef unsigned int u32;

__device__ __forceinline__ u64 pack2(float x, float y) {
    u64 r; asm("mov.b64 %0, {%1, %2};" : "=l"(r) : "f"(x), "f"(y)); return r;
}
__device__ __forceinline__ u64 pack2dup(float x) {
    u64 r; asm("mov.b64 %0, {%1, %1};" : "=l"(r) : "f"(x)); return r;
}
__device__ __forceinline__ void unpack2(u64 v, float& x, float& y) {
    asm("mov.b64 {%0, %1}, %2;" : "=f"(x), "=f"(y) : "l"(v));
}
__device__ __forceinline__ u64 ffma2(u64 a, u64 b, u64 c) {
    u64 d; asm("fma.rn.f32x2 %0, %1, %2, %3;" : "=l"(d) : "l"(a), "l"(b), "l"(c));
    return d;
}

#define HS 36   // H row stride

// K1 pool layout (floats), 7744 total:
//  At8 (1024 u32) @0 | H0 @1024..3328 | H1 @3328..5632 | WB @5632..7744
//  WB: w1 +0 (1024), b1 +1024 (32), w2 +1056 (1024), b2 +2080 (32)
#define P_H0   1024
#define P_H1   3328
#define P_WB   5632

#define MAXB 4096
__device__ float g_pool_scratch[MAXB * 320];   // [g][ci*10 + r]

// ---- weight staging (pipelined into compute phases) ----
__device__ __forceinline__ void stage_w1(const float* __restrict__ W1,
                                         const float* __restrict__ B1,
                                         float* __restrict__ WB, int din, int t)
{
    for (int idx = t; idx < din * 8; idx += 128)
        *(float4*)(WB + idx * 4) = *(const float4*)(W1 + idx * 4);
    if (t < 32) WB[1024 + t] = B1[t];
}
__device__ __forceinline__ void stage_w2(const float* __restrict__ W2,
                                         const float* __restrict__ B2,
                                         float* __restrict__ WB, int t)
{
    for (int idx = t; idx < 256; idx += 128)
        *(float4*)(WB + 1056 + idx * 4) = *(const float4*)(W2 + idx * 4);
    if (t >= 32 && t < 64) WB[2080 + (t - 32)] = B2[t - 32];
}

// ---- agg: Z[n][c] = sum_k A[n][k]*H[k][c]; A byte-packed (incl. diag) ----
template<int W>
__device__ __forceinline__ void agg_frag(const u32* __restrict__ At8,
                                         const float* __restrict__ H,
                                         float* __restrict__ Z, int t)
{
    constexpr int PP = W / 16;
    const int warp = t >> 5, lane = t & 31;
    const int ni = lane >> 2, ci = lane & 3;
    const int nhalf = (warp & 1) * 32;
    const int chalf = (warp >> 1) * (W / 2);
    const int c0 = chalf + ci * (2 * PP);

    u64 acc[4][PP];
    #pragma unroll
    for (int g = 0; g < 4; g++)
        #pragma unroll
        for (int p = 0; p < PP; p++) acc[g][p] = 0ull;

    #pragma unroll 2
    for (int kb = 0; kb < 16; kb++) {
        u32 a4[4];
        #pragma unroll
        for (int g = 0; g < 4; g++)
            a4[g] = At8[kb * 64 + nhalf + ni + 8 * g];
        #pragma unroll
        for (int j = 0; j < 4; j++) {
            const int k = 4 * kb + j;
            u64 h[PP];
            if (PP == 2) {
                const float4 hv = *(const float4*)&H[k * HS + c0];
                h[0] = pack2(hv.x, hv.y); h[1] = pack2(hv.z, hv.w);
            } else {
                const float2 hv = *(const float2*)&H[k * HS + c0];
                h[0] = pack2(hv.x, hv.y);
            }
            #pragma unroll
            for (int g = 0; g < 4; g++) {
                const float af = (float)((a4[g] >> (8 * j)) & 0xffu);
                const u64 ad = pack2dup(af);
                #pragma unroll
                for (int p = 0; p < PP; p++)
                    acc[g][p] = ffma2(ad, h[p], acc[g][p]);
            }
        }
    }
    #pragma unroll
    for (int g = 0; g < 4; g++) {
        const int n = nhalf + ni + 8 * g;
        if (PP == 2) {
            float x0, y0, x1, y1;
            unpack2(acc[g][0], x0, y0); unpack2(acc[g][1], x1, y1);
            *(float4*)&Z[n * HS + c0] = make_float4(x0, y0, x1, y1);
        } else {
            float x0, y0;
            unpack2(acc[g][0], x0, y0);
            *(float2*)&Z[n * HS + c0] = make_float2(x0, y0);
        }
    }
}

// ---- gemm: Out[n][o] = relu(B[o] + sum_k Zin[n][k]*W[k][o]); 64x32 ----
template<int DIN>
__device__ __forceinline__ void gemm_frag(const float* __restrict__ Zin,
                                          float* __restrict__ Out,
                                          const float* __restrict__ W,
                                          const float* __restrict__ B, int t)
{
    const int warp = t >> 5, lane = t & 31;
    const int ni = lane >> 2, oi = lane & 3;
    const int nhalf = (warp & 1) * 32;
    const int o0 = (warp >> 1) * 16 + 4 * oi;

    u64 acc[4][2];
    {
        const float4 b4 = *(const float4*)&B[o0];
        const u64 b01 = pack2(b4.x, b4.y), b23 = pack2(b4.z, b4.w);
        #pragma unroll
        for (int g = 0; g < 4; g++) { acc[g][0] = b01; acc[g][1] = b23; }
    }
    #pragma unroll
    for (int kb = 0; kb < DIN / 4; kb++) {
        float4 zf[4];
        #pragma unroll
        for (int g = 0; g < 4; g++)
            zf[g] = *(const float4*)&Zin[(nhalf + ni + 8 * g) * HS + 4 * kb];
        #pragma unroll
        for (int j = 0; j < 4; j++) {
            const int k = 4 * kb + j;
            const float4 wv = *(const float4*)&W[k * 32 + o0];
            const u64 w01 = pack2(wv.x, wv.y), w23 = pack2(wv.z, wv.w);
            #pragma unroll
            for (int g = 0; g < 4; g++) {
                const float a = (j == 0) ? zf[g].x : (j == 1) ? zf[g].y :
                                (j == 2) ? zf[g].z : zf[g].w;
                const u64 ad = pack2dup(a);
                acc[g][0] = ffma2(ad, w01, acc[g][0]);
                acc[g][1] = ffma2(ad, w23, acc[g][1]);
            }
        }
    }
    #pragma unroll
    for (int g = 0; g < 4; g++) {
        float x0, y0, x1, y1;
        unpack2(acc[g][0], x0, y0); unpack2(acc[g][1], x1, y1);
        *(float4*)&Out[(nhalf + ni + 8 * g) * HS + o0] =
            make_float4(fmaxf(x0, 0.f), fmaxf(y0, 0.f),
                        fmaxf(x1, 0.f), fmaxf(y1, 0.f));
    }
}

// ============================================================
// K1: adjacency + GIN + SortPooling -> g_pool_scratch
// ============================================================
__global__ void __launch_bounds__(128, 7)
gin_kernel(
    const int* __restrict__ labels,
    const int* __restrict__ src,
    const int* __restrict__ dst,
    const float* __restrict__ emb,
    const float* __restrict__ w1_0, const float* __restrict__ b1_0,
    const float* __restrict__ w2_0, const float* __restrict__ b2_0,
    const float* __restrict__ w1_1, const float* __restrict__ b1_1,
    const float* __restrict__ w2_1, const float* __restrict__ b2_1,
    const float* __restrict__ w1_2, const float* __restrict__ b1_2,
    const float* __restrict__ w2_2, const float* __restrict__ b2_2)
{
    __shared__ __align__(16) float pool[7744];
    __shared__ int nor[10];

    u32*   At8 = (u32*)pool;
    float* H0  = pool + P_H0;
    float* H1  = pool + P_H1;
    float* WB  = pool + P_WB;

    const int g = blockIdx.x;
    const int t = threadIdx.x;

    // phase 0: zero At8 + prestage layer-0 weights
    {
        const uint4 z4 = make_uint4(0u, 0u, 0u, 0u);
        *(uint4*)(At8 + t * 4)         = z4;
        *(uint4*)(At8 + (t + 128) * 4) = z4;
    }
    stage_w1(w1_0, b1_0, WB, 16, t);
    stage_w2(w2_0, b2_0, WB, t);
    __syncthreads();

    // edges + diagonal into byte-packed At8; embedding load
    {
        const int4* s4p = (const int4*)(src + ((long)g << 10));
        const int4* d4p = (const int4*)(dst + ((long)g << 10));
        #pragma unroll
        for (int i = 0; i < 2; i++) {
            const int4 s = s4p[t + i * 128];
            const int4 d = d4p[t + i * 128];
            const int sx = s.x & 63, sy = s.y & 63, sz = s.z & 63, sw = s.w & 63;
            atomicAdd(&At8[(sx >> 2) * 64 + (d.x & 63)], 1u << (8 * (sx & 3)));
            atomicAdd(&At8[(sy >> 2) * 64 + (d.y & 63)], 1u << (8 * (sy & 3)));
            atomicAdd(&At8[(sz >> 2) * 64 + (d.z & 63)], 1u << (8 * (sz & 3)));
            atomicAdd(&At8[(sw >> 2) * 64 + (d.w & 63)], 1u << (8 * (sw & 3)));
        }
        if (t < 64) atomicAdd(&At8[(t >> 2) * 64 + t], 1u << (8 * (t & 3)));
    }
    {
        const int n = t >> 1, c0 = (t & 1) * 8;
        const float4 v0 = *(const float4*)(emb + labels[(g << 6) + n] * 16 + c0);
        const float4 v1 = *(const float4*)(emb + labels[(g << 6) + n] * 16 + c0 + 4);
        *(float4*)(H0 + n * HS + c0)     = v0;
        *(float4*)(H0 + n * HS + c0 + 4) = v1;
    }
    __syncthreads();

    // layer 0
    agg_frag<16>(At8, H0, H1, t);
    __syncthreads();
    gemm_frag<16>(H1, H0, WB, WB + 1024, t);
    __syncthreads();
    gemm_frag<32>(H0, H1, WB + 1056, WB + 2080, t);
    stage_w1(w1_1, b1_1, WB, 32, t);
    __syncthreads();

    // layer 1 (cur = H1)
    agg_frag<32>(At8, H1, H0, t);
    stage_w2(w2_1, b2_1, WB, t);
    __syncthreads();
    gemm_frag<32>(H0, H1, WB, WB + 1024, t);
    __syncthreads();
    gemm_frag<32>(H1, H0, WB + 1056, WB + 2080, t);
    stage_w1(w1_2, b1_2, WB, 32, t);
    __syncthreads();

    // layer 2 (cur = H0)
    agg_frag<32>(At8, H0, H1, t);
    stage_w2(w2_2, b2_2, WB, t);
    __syncthreads();
    gemm_frag<32>(H1, H0, WB, WB + 1024, t);
    __syncthreads();
    gemm_frag<32>(H0, H1, WB + 1056, WB + 2080, t);   // FINAL -> H1
    __syncthreads();

    float* cur = H1;

    // SortPooling: stable rank by channel 31 desc, keep 10
    if (t < 64) {
        const float key = cur[t * HS + 31];
        int r = 0;
        for (int m = 0; m < 64; m++) {
            const float km = cur[m * HS + 31];
            r += (km > key) || (km == key && m < t);
        }
        if (r < 10) nor[r] = t;
    }
    __syncthreads();

    // write pooled features [ci][r] to global scratch (coalesced)
    for (int idx = t; idx < 320; idx += 128) {
        const int ci = idx / 10, r = idx - ci * 10;
        g_pool_scratch[(long)g * 320 + idx] = cur[nor[r] * HS + ci];
    }
}

// ============================================================
// K2: conv1 + maxpool + conv2 + mean + scorer; warp-per-graph
// ============================================================
// smem layout (floats), 13392 total:
#define C1W 0       // 32 x 165 = 5280
#define C1B 5280    // 32
#define C2W 5312    // 16 x 165 = 2640
#define C2B 7952    // 16
#define SW1 7968    // 256
#define SB1 8224    // 16
#define SW2 8240    // 16
#define SB2 8256    // 1
#define PS  8272    // 8 x 384
#define YB  11344   // 8 x 256
#define K2_SMEM 13392

__global__ void __launch_bounds__(256)
conv_kernel(
    const float* __restrict__ conv1_w, const float* __restrict__ conv1_b,
    const float* __restrict__ conv2_w, const float* __restrict__ conv2_b,
    const float* __restrict__ sc_w1, const float* __restrict__ sc_b1,
    const float* __restrict__ sc_w2, const float* __restrict__ sc_b2,
    float* __restrict__ out, int B)
{
    extern __shared__ __align__(16) float s[];
    const int t = threadIdx.x;
    const int w = t >> 5, lane = t & 31;

    // ---- stage all weights once per CTA (8 graphs) ----
    for (int idx = t; idx < 5120; idx += 256) {
        const int co = idx / 160, r = idx - co * 160;
        s[C1W + co * 165 + r] = conv1_w[idx];
    }
    for (int idx = t; idx < 2560; idx += 256) {
        const int co = idx / 160, r = idx - co * 160;
        s[C2W + co * 165 + r] = conv2_w[idx];
    }
    if (t < 32)              s[C1B + t] = conv1_b[t];
    if (t >= 32 && t < 48)   s[C2B + (t - 32)] = conv2_b[t - 32];
    if (t >= 48 && t < 64)   s[SB1 + (t - 48)] = sc_b1[t - 48];
    s[SW1 + t] = sc_w1[t];   // t covers 0..255 exactly
    if (t >= 224 && t < 240) s[SW2 + (t - 224)] = sc_w2[t - 224];
    if (t == 255)            s[SB2] = sc_b2[0];
    __syncthreads();

    const int g = blockIdx.x * 8 + w;
    if (g >= B) return;

    float* ps = s + PS + w * 384;   // pooledT [ci*12 + r], r<10 valid
    float* yb = s + YB + w * 256;   // ybufT   [ci*8 + q],  q<5 valid

    // ---- load pooled features (coalesced) into padded smem ----
    for (int i = lane; i < 384; i += 32) ps[i] = 0.f;
    __syncwarp();
    for (int i = lane; i < 320; i += 32) {
        const int ci = i / 10, r = i - ci * 10;
        ps[ci * 12 + r] = g_pool_scratch[(long)g * 320 + i];
    }
    __syncwarp();

    // ---- conv1 (lane = co) + bias + relu + maxpool ----
    {
        float acc[10];
        #pragma unroll
        for (int p = 0; p < 10; p++) acc[p] = 0.f;
        for (int ci = 0; ci < 32; ci++) {
            float w5[5];
            #pragma unroll
            for (int k = 0; k < 5; k++) w5[k] = s[C1W + lane * 165 + ci * 5 + k];
            const float4 va = *(const float4*)&ps[ci * 12];
            const float4 vb = *(const float4*)&ps[ci * 12 + 4];
            const float4 vc = *(const float4*)&ps[ci * 12 + 8];
            const float v[12] = { va.x, va.y, va.z, va.w, vb.x, vb.y, vb.z, vb.w,
                                  vc.x, vc.y, vc.z, vc.w };
            #pragma unroll
            for (int p = 0; p < 10; p++) {
                #pragma unroll
                for (int k = 0; k < 5; k++) {
                    const int idx = p + k - 2;
                    if (idx >= 0) acc[p] = fmaf(w5[k], v[idx], acc[p]);
                }
            }
        }
        const float b = s[C1B + lane];
        #pragma unroll
        for (int q = 0; q < 5; q++) {
            const float v0 = fmaxf(acc[2 * q] + b, 0.f);
            const float v1 = fmaxf(acc[2 * q + 1] + b, 0.f);
            yb[lane * 8 + q] = fmaxf(v0, v1);
        }
        yb[lane * 8 + 5] = 0.f;
        yb[lane * 8 + 6] = 0.f;
        yb[lane * 8 + 7] = 0.f;
    }
    __syncwarp();

    // ---- conv2 (co = lane&15; hi lanes mirror lo lanes) + mean ----
    float feat;
    {
        const int co = lane & 15;
        float a2[5];
        #pragma unroll
        for (int p = 0; p < 5; p++) a2[p] = s[C2B + co];
        for (int ci = 0; ci < 32; ci++) {
            float w5[5];
            #pragma unroll
            for (int k = 0; k < 5; k++) w5[k] = s[C2W + co * 165 + ci * 5 + k];
            const float4 ya = *(const float4*)&yb[ci * 8];
            const float y4 = yb[ci * 8 + 4];
            const float a[9] = { 0.f, 0.f, ya.x, ya.y, ya.z, ya.w, y4, 0.f, 0.f };
            #pragma unroll
            for (int p = 0; p < 5; p++)
                #pragma unroll
                for (int k = 0; k < 5; k++)
                    a2[p] = fmaf(w5[k], a[p + k], a2[p]);
        }
        float sum = 0.f;
        #pragma unroll
        for (int p = 0; p < 5; p++) sum += fmaxf(a2[p], 0.f);
        feat = 0.2f * sum;
    }

    // ---- scorer MLP via shuffles (feat valid in lanes 0..15) ----
    {
        const int o = lane & 15;
        float a = s[SB1 + o];
        #pragma unroll
        for (int i = 0; i < 16; i++)
            a = fmaf(__shfl_sync(0xffffffffu, feat, i), s[SW1 + i * 16 + o], a);
        float hid = fmaxf(a, 0.f) * s[SW2 + o];
        if (lane >= 16) hid = 0.f;
        #pragma unroll
        for (int off = 16; off; off >>= 1)
            hid += __shfl_down_sync(0xffffffffu, hid, off);
        if (lane == 0) out[g] = hid + s[SB2];
    }
}

extern "C" void kernel_launch(void* const* d_in, const int* in_sizes, int n_in,
                              void* d_out, int out_size)
{
    const int B = in_sizes[0] / 64;

    gin_kernel<<<B, 128>>>(
        (const int*)d_in[0], (const int*)d_in[1], (const int*)d_in[2],
        (const float*)d_in[3],
        (const float*)d_in[4],  (const float*)d_in[5],
        (const float*)d_in[6],  (const float*)d_in[7],
        (const float*)d_in[8],  (const float*)d_in[9],
        (const float*)d_in[10], (const float*)d_in[11],
        (const float*)d_in[12], (const float*)d_in[13],
        (const float*)d_in[14], (const float*)d_in[15]);

    const int smem = K2_SMEM * sizeof(float);   // 53568 B
    cudaFuncSetAttribute(conv_kernel,
                         cudaFuncAttributeMaxDynamicSharedMemorySize, smem);
    conv_kernel<<<(B + 7) / 8, 256, smem>>>(
        (const float*)d_in[16], (const float*)d_in[17],
        (const float*)d_in[18], (const float*)d_in[19],
        (const float*)d_in[20], (const float*)d_in[21],
        (const float*)d_in[22], (const float*)d_in[23],
        (float*)d_out, B);
}